// round 6
// baseline (speedup 1.0000x reference)
#include <cuda_runtime.h>
#include <cstdint>

// x: (128, 32, 2, 64, 64) fp32 -> 4096 tiles of (2, 64, 64).
// plaq[i][j] = t0[i][j] + t1[(i+1)%64][j] - t0[i][(j+1)%64] - t1[i][j]
// out[tile] = mean(cos(plaq))
//
// cp.async double-buffered pipeline (DRAM decoupling lives in the async copy
// engine, not the register file) + cheap compute body (float4 LDS, j+1 roll
// via lane shuffle, i+1 roll = second s1 read; smem makes the re-read free).
// 456 CTAs (3/SM) x 64KB smem: >=2 tiles in flight per CTA, 6 per SM.

#define THREADS 256
#define NUM_TILES 4096
#define TILE_FLOATS 8192              // 2 * 64 * 64
#define GRID_CTAS 456                 // 152 SMs * 3 CTAs/SM

__device__ __forceinline__ void cp_async16(float* dst_smem, const float* src) {
    uint32_t d = (uint32_t)__cvta_generic_to_shared(dst_smem);
    asm volatile("cp.async.cg.shared.global [%0], [%1], 16;\n"
                 :: "r"(d), "l"(src));
}
__device__ __forceinline__ void cp_commit() {
    asm volatile("cp.async.commit_group;\n" ::: "memory");
}
template <int N>
__device__ __forceinline__ void cp_wait() {
    asm volatile("cp.async.wait_group %0;\n" :: "n"(N) : "memory");
}

// Prefetch one tile (2048 float4) into an smem buffer. 8 x 16B per thread.
__device__ __forceinline__ void prefetch_tile(float* smbuf, const float* gtile, int tid) {
    #pragma unroll
    for (int j = 0; j < 8; j++) {
        const int v = tid + j * THREADS;   // float4 index 0..2047
        cp_async16(smbuf + v * 4, gtile + v * 4);
    }
}

__global__ __launch_bounds__(THREADS) void plaq_trace_pipe2_kernel(
    const float* __restrict__ x, float* __restrict__ out)
{
    extern __shared__ float sm[];          // 2 * TILE_FLOATS
    __shared__ float warp_sums[THREADS / 32];

    const int tid  = threadIdx.x;
    const int lane = tid & 31;
    const int wid  = tid >> 5;
    const int src  = (lane & 16) | ((lane + 1) & 15);   // right-neighbor lane

    int t = blockIdx.x;
    if (t >= NUM_TILES) return;

    prefetch_tile(sm, x + (size_t)t * TILE_FLOATS, tid);
    cp_commit();

    int buf = 0;
    while (true) {
        const int tn = t + GRID_CTAS;
        const bool has_next = (tn < NUM_TILES);

        if (has_next) {
            // Fill the other buffer (freed by last iteration's trailing sync).
            prefetch_tile(sm + (buf ^ 1) * TILE_FLOATS,
                          x + (size_t)tn * TILE_FLOATS, tid);
            cp_commit();
            cp_wait<1>();                  // current tile complete
        } else {
            cp_wait<0>();
        }
        __syncthreads();

        const float4* __restrict__ s0 = (const float4*)(sm + buf * TILE_FLOATS);
        const float4* __restrict__ s1 = s0 + 1024;

        float sum = 0.0f;
        #pragma unroll
        for (int k = 0; k < 4; k++) {
            const int g  = tid + k * THREADS;      // float4 group 0..1023
            const int i  = g >> 4;                 // row
            const int jg = g & 15;                 // float4 col
            const int g1 = (((i + 1) & 63) << 4) | jg;

            const float4 A0 = s0[g];
            const float4 A1 = s1[g];
            const float4 B1 = s1[g1];
            const float nx = __shfl_sync(0xFFFFFFFFu, A0.x, src);

            sum += __cosf(A0.x + B1.x - A0.y - A1.x);
            sum += __cosf(A0.y + B1.y - A0.z - A1.y);
            sum += __cosf(A0.z + B1.z - A0.w - A1.z);
            sum += __cosf(A0.w + B1.w - nx   - A1.w);
        }

        #pragma unroll
        for (int off = 16; off > 0; off >>= 1)
            sum += __shfl_xor_sync(0xFFFFFFFFu, sum, off);
        if (lane == 0) warp_sums[wid] = sum;
        __syncthreads();

        if (wid == 0) {
            float s = (lane < (THREADS / 32)) ? warp_sums[lane] : 0.0f;
            #pragma unroll
            for (int off = 4; off > 0; off >>= 1)
                s += __shfl_xor_sync(0xFFFFFFFFu, s, off);
            if (lane == 0) out[t] = s * (1.0f / 4096.0f);
        }

        if (!has_next) break;
        buf ^= 1;
        t = tn;
        __syncthreads();   // all threads done reading old buf before refill
    }
}

extern "C" void kernel_launch(void* const* d_in, const int* in_sizes, int n_in,
                              void* d_out, int out_size)
{
    const float* x = (const float*)d_in[0];
    float* out = (float*)d_out;

    static bool attr_set = false;
    if (!attr_set) {
        cudaFuncSetAttribute(plaq_trace_pipe2_kernel,
                             cudaFuncAttributeMaxDynamicSharedMemorySize,
                             2 * TILE_FLOATS * sizeof(float));
        attr_set = true;
    }

    plaq_trace_pipe2_kernel<<<GRID_CTAS, THREADS,
                              2 * TILE_FLOATS * sizeof(float)>>>(x, out);
}

// round 7
// speedup vs baseline: 1.0106x; 1.0106x over previous
#include <cuda_runtime.h>

// x: (128, 32, 2, 64, 64) fp32 -> 4096 tiles of (2, 64, 64).
// plaq[i][j] = t0[i][j] + t1[(i+1)%64][j] - t0[i][(j+1)%64] - t1[i][j]
// out[tile] = mean(cos(plaq))
//
// Persistent single-wave (1024 CTAs x 256 thr, 7 CTAs/SM, 4 tiles/CTA) with a
// depth-2 REGISTER software pipeline: while computing chunk c, loads for
// chunk c+1 are in flight; the last chunk of round r issues chunk 0 of round
// r+1, so the warp keeps loads outstanding across the reduction + barriers.
// j+1 roll in-register via lane shuffle ((l&16)|((l+1)&15)); i+1 roll is a
// second t1 read (L1/L2 hit). 24 live load-floats -> fits 36-reg budget.

#define THREADS 256
#define GRID_CTAS 1024
#define ROUNDS 4            // 4096 tiles / 1024 CTAs

struct Chunk { float4 A0, A1, B1; };

__device__ __forceinline__ void load_chunk(Chunk& ch, const float4* __restrict__ t0,
                                           int tid, int c)
{
    const int g  = tid + c * THREADS;       // float4 group 0..1023
    const int i  = g >> 4;                  // row
    const int g1 = (((i + 1) & 63) << 4) | (g & 15);
    const float4* __restrict__ t1 = t0 + 1024;
    ch.A0 = t0[g];
    ch.A1 = t1[g];
    ch.B1 = t1[g1];
}

__device__ __forceinline__ float chunk_cos(const Chunk& ch, int src)
{
    const float nx = __shfl_sync(0xFFFFFFFFu, ch.A0.x, src);
    float s;
    s  = __cosf(ch.A0.x + ch.B1.x - ch.A0.y - ch.A1.x);
    s += __cosf(ch.A0.y + ch.B1.y - ch.A0.z - ch.A1.y);
    s += __cosf(ch.A0.z + ch.B1.z - ch.A0.w - ch.A1.z);
    s += __cosf(ch.A0.w + ch.B1.w - nx      - ch.A1.w);
    return s;
}

__global__ __launch_bounds__(THREADS, 7) void plaq_trace_swpipe_kernel(
    const float4* __restrict__ x4, float* __restrict__ out)
{
    const int tid  = threadIdx.x;
    const int lane = tid & 31;
    const int wid  = tid >> 5;
    const int src  = (lane & 16) | ((lane + 1) & 15);

    __shared__ float warp_sums[THREADS / 32];

    const float4* __restrict__ t0 = x4 + (size_t)blockIdx.x * 2048;

    Chunk cur, nxt;
    load_chunk(cur, t0, tid, 0);            // prologue: round 0, chunk 0

    #pragma unroll 1
    for (int r = 0; r < ROUNDS; r++) {
        const float4* __restrict__ t0n =
            x4 + (size_t)(blockIdx.x + (r + 1) * GRID_CTAS) * 2048;

        float sum = 0.0f;
        #pragma unroll
        for (int c = 0; c < 4; c++) {
            if (c < 3) {
                load_chunk(nxt, t0, tid, c + 1);
            } else if (r + 1 < ROUNDS) {
                load_chunk(nxt, t0n, tid, 0);   // cross-round prefetch
            }
            sum += chunk_cos(cur, src);
            cur = nxt;
        }

        #pragma unroll
        for (int off = 16; off > 0; off >>= 1)
            sum += __shfl_xor_sync(0xFFFFFFFFu, sum, off);
        if (lane == 0) warp_sums[wid] = sum;
        __syncthreads();

        if (wid == 0) {
            float s = (lane < (THREADS / 32)) ? warp_sums[lane] : 0.0f;
            #pragma unroll
            for (int off = 4; off > 0; off >>= 1)
                s += __shfl_xor_sync(0xFFFFFFFFu, s, off);
            if (lane == 0) out[blockIdx.x + r * GRID_CTAS] = s * (1.0f / 4096.0f);
        }
        __syncthreads();                    // warp_sums reuse guard

        t0 = t0n;
    }
}

extern "C" void kernel_launch(void* const* d_in, const int* in_sizes, int n_in,
                              void* d_out, int out_size)
{
    const float4* x4 = (const float4*)d_in[0];
    float* out = (float*)d_out;
    plaq_trace_swpipe_kernel<<<GRID_CTAS, THREADS>>>(x4, out);
}